// round 4
// baseline (speedup 1.0000x reference)
#include <cuda_runtime.h>
#include <math.h>

#define BB 32768
#define KK 32
#define DD 256
#define HH 8
#define DKK 32
#define FFD 1024

// ---------------- scratch (static device allocations; no cudaMalloc) ----------------
__device__ float g_xln[BB * DD];            // LN1(x_anc)
__device__ float g_Q[BB * DD];              // xln @ W_q
__device__ float g_Qt[(size_t)BB * HH * DD];// per-head Q_h @ Wk_h^T (scaled 1/sqrt(dk))
__device__ float g_y[(size_t)BB * HH * DD]; // attn-weighted neighbor sums
__device__ float g_v[BB * DD];              // per-head y_h @ Wv_h (concat)
__device__ float g_x[BB * DD];              // x_anc + v @ W_o
__device__ float g_hln[BB * DD];            // LN2(x)
__device__ float g_act[(size_t)BB * FFD];   // gelu(hln @ ff1 + b1)
__device__ float g_WkT[DD * DD];            // WkT[h*32+j][d] = W_k[d][h*32+j]

// ---------------- tiny prep: transpose W_k ----------------
__global__ void prep_wkt(const float* __restrict__ Wk, float* __restrict__ WkT) {
    int i = blockIdx.x * 256 + threadIdx.x;      // 0..65535
    int d = i & 255;
    int hj = i >> 8;
    WkT[hj * 256 + d] = Wk[d * 256 + hj];
}

// ---------------- row layernorm: 1 warp per row ----------------
__global__ void __launch_bounds__(256) ln_kernel(const float* __restrict__ X,
                                                 const float* __restrict__ gam,
                                                 const float* __restrict__ bet,
                                                 float* __restrict__ Y) {
    int row = blockIdx.x * 8 + (threadIdx.x >> 5);
    int l = threadIdx.x & 31;
    const float4* xr = (const float4*)(X + (size_t)row * DD);
    float4 v0 = xr[l];
    float4 v1 = xr[l + 32];
    float s = v0.x + v0.y + v0.z + v0.w + v1.x + v1.y + v1.z + v1.w;
    float sq = v0.x * v0.x + v0.y * v0.y + v0.z * v0.z + v0.w * v0.w +
               v1.x * v1.x + v1.y * v1.y + v1.z * v1.z + v1.w * v1.w;
#pragma unroll
    for (int o = 16; o > 0; o >>= 1) {
        s += __shfl_xor_sync(0xffffffffu, s, o);
        sq += __shfl_xor_sync(0xffffffffu, sq, o);
    }
    float mu = s * (1.0f / 256.0f);
    float var = sq * (1.0f / 256.0f) - mu * mu;
    float inv = rsqrtf(var + 1e-5f);
    float4 g0 = ((const float4*)gam)[l];
    float4 g1 = ((const float4*)gam)[l + 32];
    float4 b0 = ((const float4*)bet)[l];
    float4 b1 = ((const float4*)bet)[l + 32];
    float4 o0, o1;
    o0.x = (v0.x - mu) * inv * g0.x + b0.x;
    o0.y = (v0.y - mu) * inv * g0.y + b0.y;
    o0.z = (v0.z - mu) * inv * g0.z + b0.z;
    o0.w = (v0.w - mu) * inv * g0.w + b0.w;
    o1.x = (v1.x - mu) * inv * g1.x + b1.x;
    o1.y = (v1.y - mu) * inv * g1.y + b1.y;
    o1.z = (v1.z - mu) * inv * g1.z + b1.z;
    o1.w = (v1.w - mu) * inv * g1.w + b1.w;
    float4* yr = (float4*)(Y + (size_t)row * DD);
    yr[l] = o0;
    yr[l + 32] = o1;
}

// ---------------- generic FFMA GEMM ----------------
// C[r,c] = epilogue(alpha * sum_k A[r,k]*Bm[k,c])
// EPI 0: alpha*acc
// EPI 1: t = acc + bias[c]; t * normcdf(t)          (exact GELU)
// EPI 2: acc + bias[c] + R[r*ldr+c]                 (final residual + bias)
// EPI 3: acc + R[r*ldr+c]                           (residual)
// blockIdx.z selects a "head": A += z*sA, Bm += z*sB, C += z*sC.
template <int BM, int BN, int BK, int TM, int TN, int EPI>
__global__ void __launch_bounds__(256) gemm_k(
    const float* __restrict__ A, int lda, long sA,
    const float* __restrict__ Bm, int ldb, long sB,
    float* __restrict__ C, int ldc, long sC,
    int Kd, float alpha,
    const float* __restrict__ bias,
    const float* __restrict__ R, int ldr) {
    __shared__ float As[BK][BM + 4];
    __shared__ float Bs[BK][BN + 4];

    A += (size_t)blockIdx.z * sA;
    Bm += (size_t)blockIdx.z * sB;
    C += (size_t)blockIdx.z * sC;

    const int t = threadIdx.x;
    const int tx = t % (BN / TN);   // 16 col-groups
    const int ty = t / (BN / TN);   // 16 row-groups
    const int row0 = blockIdx.y * BM;
    const int col0 = blockIdx.x * BN;

    float acc[TM][TN];
#pragma unroll
    for (int i = 0; i < TM; i++)
#pragma unroll
        for (int j = 0; j < TN; j++) acc[i][j] = 0.0f;

    for (int k0 = 0; k0 < Kd; k0 += BK) {
        // A tile: BM x BK (store transposed)
        constexpr int AF4 = BM * BK / 4;
#pragma unroll
        for (int i = t; i < AF4; i += 256) {
            int r = i / (BK / 4);
            int kk = (i % (BK / 4)) * 4;
            float4 v = *(const float4*)&A[(size_t)(row0 + r) * lda + k0 + kk];
            As[kk + 0][r] = v.x;
            As[kk + 1][r] = v.y;
            As[kk + 2][r] = v.z;
            As[kk + 3][r] = v.w;
        }
        // B tile: BK x BN
        constexpr int BF4 = BK * BN / 4;
#pragma unroll
        for (int i = t; i < BF4; i += 256) {
            int kk = i / (BN / 4);
            int nn = (i % (BN / 4)) * 4;
            *(float4*)&Bs[kk][nn] = *(const float4*)&Bm[(size_t)(k0 + kk) * ldb + col0 + nn];
        }
        __syncthreads();

#pragma unroll 8
        for (int kk = 0; kk < BK; kk++) {
            float a[TM], b[TN];
#pragma unroll
            for (int i = 0; i < TM; i += 4) {
                float4 v = *(const float4*)&As[kk][ty * TM + i];
                a[i] = v.x; a[i + 1] = v.y; a[i + 2] = v.z; a[i + 3] = v.w;
            }
            if constexpr (TN == 4) {
                float4 v = *(const float4*)&Bs[kk][tx * TN];
                b[0] = v.x; b[1] = v.y; b[2] = v.z; b[3] = v.w;
            } else {
                float2 v = *(const float2*)&Bs[kk][tx * TN];
                b[0] = v.x; b[1] = v.y;
            }
#pragma unroll
            for (int i = 0; i < TM; i++)
#pragma unroll
                for (int j = 0; j < TN; j++) acc[i][j] = fmaf(a[i], b[j], acc[i][j]);
        }
        __syncthreads();
    }

#pragma unroll
    for (int i = 0; i < TM; i++) {
        int r = row0 + ty * TM + i;
#pragma unroll
        for (int j = 0; j < TN; j++) {
            int c = col0 + tx * TN + j;
            float v = alpha * acc[i][j];
            if constexpr (EPI == 1) {
                v = v + bias[c];
                v = v * normcdff(v);
            } else if constexpr (EPI == 2) {
                v = v + bias[c] + R[(size_t)r * ldr + c];
            } else if constexpr (EPI == 3) {
                v = v + R[(size_t)r * ldr + c];
            }
            C[(size_t)r * ldc + c] = v;
        }
    }
}

// ---------------- fused single-query attention (per-b CTA) ----------------
// reads Qt[b] (8x256, pre-scaled by 1/sqrt(dk)) and x_nei[b] (32x256);
// computes scores, softmax over K=32, and y[b,h,:] = sum_k attn*x_nei[b,k,:].
__global__ void __launch_bounds__(256) attn_kernel(const float* __restrict__ xnei,
                                                   const float* __restrict__ Qt,
                                                   float* __restrict__ y) {
    const int b = blockIdx.x;
    __shared__ float xs[KK][260];        // padded: conflict-free LDS.128 both ways
    __shared__ float qs[HH][260];
    __shared__ float spart[2][HH][KK];
    __shared__ float attn_s[HH][KK];
    const int t = threadIdx.x;

    // load x_nei[b] (32x256 fp32 = 2048 float4)
    const float4* gx = (const float4*)(xnei + (size_t)b * (KK * DD));
#pragma unroll
    for (int i = 0; i < 8; i++) {
        int idx = i * 256 + t;
        int k = idx >> 6;
        int c4 = idx & 63;
        *(float4*)&xs[k][c4 * 4] = gx[idx];
    }
    // load Qt[b] (8x256 = 512 float4)
    const float4* gq = (const float4*)(Qt + (size_t)b * (HH * DD));
#pragma unroll
    for (int i = 0; i < 2; i++) {
        int idx = i * 256 + t;
        int hh = idx >> 6;
        int c4 = idx & 63;
        *(float4*)&qs[hh][c4 * 4] = gq[idx];
    }
    __syncthreads();

    // scores: thread = (d-half, head-pair, k); each computes 2 partial dots over 128 d's
    {
        int w = t >> 5, l = t & 31;
        int half = w >> 2;
        int h0 = (w & 3) * 2;
        int k = l;
        int dbase = half * 128;
        float s0 = 0.0f, s1 = 0.0f;
#pragma unroll
        for (int d4 = 0; d4 < 32; d4++) {
            float4 xv = *(const float4*)&xs[k][dbase + d4 * 4];
            float4 q0 = *(const float4*)&qs[h0][dbase + d4 * 4];
            float4 q1 = *(const float4*)&qs[h0 + 1][dbase + d4 * 4];
            s0 = fmaf(xv.x, q0.x, fmaf(xv.y, q0.y, fmaf(xv.z, q0.z, fmaf(xv.w, q0.w, s0))));
            s1 = fmaf(xv.x, q1.x, fmaf(xv.y, q1.y, fmaf(xv.z, q1.z, fmaf(xv.w, q1.w, s1))));
        }
        spart[half][h0][k] = s0;
        spart[half][h0 + 1][k] = s1;
    }
    __syncthreads();

    // softmax: warp w handles head w, lane = k (K = 32 = warp width)
    {
        int w = t >> 5, l = t & 31;
        float s = spart[0][w][l] + spart[1][w][l];
        float m = s;
#pragma unroll
        for (int o = 16; o > 0; o >>= 1) m = fmaxf(m, __shfl_xor_sync(0xffffffffu, m, o));
        float e = expf(s - m);
        float sum = e;
#pragma unroll
        for (int o = 16; o > 0; o >>= 1) sum += __shfl_xor_sync(0xffffffffu, sum, o);
        attn_s[w][l] = e / sum;
    }
    __syncthreads();

    // y: thread = (head-pair hp = t>>6, d-group dg = t&63), 4 d's per group
    {
        int hp = t >> 6;
        int dg = t & 63;
        int h0 = hp * 2;
        float4 a0 = make_float4(0.f, 0.f, 0.f, 0.f);
        float4 a1 = make_float4(0.f, 0.f, 0.f, 0.f);
#pragma unroll
        for (int k = 0; k < KK; k++) {
            float w0 = attn_s[h0][k];
            float w1 = attn_s[h0 + 1][k];
            float4 xv = *(const float4*)&xs[k][dg * 4];
            a0.x = fmaf(w0, xv.x, a0.x); a0.y = fmaf(w0, xv.y, a0.y);
            a0.z = fmaf(w0, xv.z, a0.z); a0.w = fmaf(w0, xv.w, a0.w);
            a1.x = fmaf(w1, xv.x, a1.x); a1.y = fmaf(w1, xv.y, a1.y);
            a1.z = fmaf(w1, xv.z, a1.z); a1.w = fmaf(w1, xv.w, a1.w);
        }
        float4* gy = (float4*)(y + (size_t)b * (HH * DD));
        gy[h0 * 64 + dg] = a0;
        gy[(h0 + 1) * 64 + dg] = a1;
    }
}

// ---------------- launch ----------------
extern "C" void kernel_launch(void* const* d_in, const int* in_sizes, int n_in,
                              void* d_out, int out_size) {
    (void)in_sizes; (void)n_in; (void)out_size;
    const float* x_anc = (const float*)d_in[0];
    const float* x_nei = (const float*)d_in[1];
    const float* W_q   = (const float*)d_in[2];
    const float* W_k   = (const float*)d_in[3];
    const float* W_v   = (const float*)d_in[4];
    const float* W_o   = (const float*)d_in[5];
    const float* ln1_g = (const float*)d_in[6];
    const float* ln1_b = (const float*)d_in[7];
    const float* ln2_g = (const float*)d_in[8];
    const float* ln2_b = (const float*)d_in[9];
    const float* ff1_w = (const float*)d_in[10];
    const float* ff1_b = (const float*)d_in[11];
    const float* ff2_w = (const float*)d_in[12];
    const float* ff2_b = (const float*)d_in[13];
    float* out = (float*)d_out;

    float *p_xln, *p_Q, *p_Qt, *p_y, *p_v, *p_x, *p_hln, *p_act, *p_WkT;
    cudaGetSymbolAddress((void**)&p_xln, g_xln);
    cudaGetSymbolAddress((void**)&p_Q, g_Q);
    cudaGetSymbolAddress((void**)&p_Qt, g_Qt);
    cudaGetSymbolAddress((void**)&p_y, g_y);
    cudaGetSymbolAddress((void**)&p_v, g_v);
    cudaGetSymbolAddress((void**)&p_x, g_x);
    cudaGetSymbolAddress((void**)&p_hln, g_hln);
    cudaGetSymbolAddress((void**)&p_act, g_act);
    cudaGetSymbolAddress((void**)&p_WkT, g_WkT);

    const float inv_sqrt_dk = 0.17677669529663687f;  // 1/sqrt(32)

    // 0) transpose W_k per head
    prep_wkt<<<DD * DD / 256, 256>>>(W_k, p_WkT);
    // 1) LN1
    ln_kernel<<<BB / 8, 256>>>(x_anc, ln1_g, ln1_b, p_xln);
    // 2) Q = xln @ W_q                         [B,256]x[256,256]
    gemm_k<128, 64, 32, 8, 4, 0><<<dim3(4, 256, 1), 256>>>(
        p_xln, 256, 0, W_q, 256, 0, p_Q, 256, 0, 256, 1.0f, nullptr, nullptr, 0);
    // 3) Qt_h = (Q_h @ Wk_h^T) / sqrt(dk)      per head: [B,32]x[32,256]
    gemm_k<128, 64, 32, 8, 4, 0><<<dim3(4, 256, 8), 256>>>(
        p_Q, 256, 32, p_WkT, 256, 32 * 256, p_Qt, 2048, 256, 32, inv_sqrt_dk,
        nullptr, nullptr, 0);
    // 4) attention: scores/softmax/weighted-sum -> y [B,H,D]
    attn_kernel<<<BB, 256>>>(x_nei, p_Qt, p_y);
    // 5) v_h = y_h @ Wv_h                      per head: [B,256]x[256,32]
    gemm_k<128, 32, 32, 8, 2, 0><<<dim3(1, 256, 8), 256>>>(
        p_y, 2048, 256, W_v, 256, 32, p_v, 256, 32, 256, 1.0f, nullptr, nullptr, 0);
    // 6) x = x_anc + v @ W_o
    gemm_k<128, 64, 32, 8, 4, 3><<<dim3(4, 256, 1), 256>>>(
        p_v, 256, 0, W_o, 256, 0, p_x, 256, 0, 256, 1.0f, nullptr, x_anc, 256);
    // 7) LN2
    ln_kernel<<<BB / 8, 256>>>(p_x, ln2_g, ln2_b, p_hln);
    // 8) act = gelu(hln @ ff1_w + ff1_b)       [B,256]x[256,1024]
    gemm_k<128, 64, 32, 8, 4, 1><<<dim3(16, 256, 1), 256>>>(
        p_hln, 256, 0, ff1_w, 1024, 0, p_act, 1024, 0, 256, 1.0f, ff1_b, nullptr, 0);
    // 9) out = x + act @ ff2_w + ff2_b         [B,1024]x[1024,256]
    gemm_k<128, 64, 32, 8, 4, 2><<<dim3(4, 256, 1), 256>>>(
        p_act, 1024, 0, ff2_w, 256, 0, out, 256, 0, 1024, 1.0f, ff2_b, p_x, 256);
}